// round 17
// baseline (speedup 1.0000x reference)
#include <cuda_runtime.h>
#include <cuda_bf16.h>
#include <cuda_fp16.h>
#include <cstdint>

#define N_NODES 50000
#define N_EDGES 1600000
#define CDIM 128
#define N_LAYERS 8

// ---------------- scratch (device globals; no allocation allowed) ----------
__device__ float  g_h [N_NODES * CDIM];    // fp32 node features (residual / fc0 input)
__device__ __half g_hwh[N_NODES * CDIM];   // fp16 transformed features (gather table)
__device__ float  g_A [N_NODES * CDIM];
__device__ float  g_B [N_NODES * CDIM];
__device__ float  g_dis[N_NODES];
__device__ int    g_deg[N_NODES];
__device__ int    g_indptr[N_NODES + 1];
__device__ int    g_cursor[N_NODES];
__device__ int    g_csr_src[N_EDGES];
__device__ int    g_csr_dst[N_EDGES];
__device__ int    g_csr_eid[N_EDGES];
__device__ float  g_csr_nrm[N_EDGES];
// transposed + bf16 hi/lo-split weights for node GEMMs: [10][n=128][k=128]
__device__ __nv_bfloat16 g_Wth[10 * 128 * 128];
__device__ __nv_bfloat16 g_Wtl[10 * 128 * 128];

// ---------------- helpers ----------------------------------------------------
__device__ __forceinline__ void mma_bf16(float d[4], const uint32_t a[4],
                                         uint32_t b0, uint32_t b1) {
    asm volatile(
        "mma.sync.aligned.m16n8k16.row.col.f32.bf16.bf16.f32 "
        "{%0,%1,%2,%3}, {%4,%5,%6,%7}, {%8,%9}, {%0,%1,%2,%3};"
        : "+f"(d[0]), "+f"(d[1]), "+f"(d[2]), "+f"(d[3])
        : "r"(a[0]), "r"(a[1]), "r"(a[2]), "r"(a[3]), "r"(b0), "r"(b1));
}
__device__ __forceinline__ void mma_fp16(float d[4], const uint32_t a[4],
                                         uint32_t b0, uint32_t b1) {
    asm volatile(
        "mma.sync.aligned.m16n8k16.row.col.f32.f16.f16.f32 "
        "{%0,%1,%2,%3}, {%4,%5,%6,%7}, {%8,%9}, {%0,%1,%2,%3};"
        : "+f"(d[0]), "+f"(d[1]), "+f"(d[2]), "+f"(d[3])
        : "r"(a[0]), "r"(a[1]), "r"(a[2]), "r"(a[3]), "r"(b0), "r"(b1));
}
__device__ __forceinline__ void ldmx4(uint32_t r[4], uint32_t addr) {
    asm volatile("ldmatrix.sync.aligned.m8n8.x4.shared.b16 {%0,%1,%2,%3}, [%4];"
                 : "=r"(r[0]), "=r"(r[1]), "=r"(r[2]), "=r"(r[3]) : "r"(addr));
}
__device__ __forceinline__ float4 f4add(float4 a, float4 b) {
    return make_float4(a.x + b.x, a.y + b.y, a.z + b.z, a.w + b.w);
}
__device__ __forceinline__ float4 f4relu(float4 a) {
    return make_float4(fmaxf(a.x, 0.f), fmaxf(a.y, 0.f), fmaxf(a.z, 0.f), fmaxf(a.w, 0.f));
}
__device__ __forceinline__ uint32_t pack_bf16(float a, float b) {
    uint32_t lo = (uint32_t)__bfloat16_as_ushort(__float2bfloat16(a));
    uint32_t hi = (uint32_t)__bfloat16_as_ushort(__float2bfloat16(b));
    return lo | (hi << 16);
}
// accumulate 8 fp16 channels (uint4) scaled by nr into two float4s
__device__ __forceinline__ void acc_h8(float4& a0, float4& a1, uint4 raw, float nr) {
    __half2 h0 = *(__half2*)&raw.x;
    __half2 h1 = *(__half2*)&raw.y;
    __half2 h2 = *(__half2*)&raw.z;
    __half2 h3 = *(__half2*)&raw.w;
    float2 f0 = __half22float2(h0);
    float2 f1 = __half22float2(h1);
    float2 f2 = __half22float2(h2);
    float2 f3 = __half22float2(h3);
    a0.x += nr * f0.x; a0.y += nr * f0.y;
    a0.z += nr * f1.x; a0.w += nr * f1.y;
    a1.x += nr * f2.x; a1.y += nr * f2.y;
    a1.z += nr * f3.x; a1.w += nr * f3.y;
}

// ---------------- setup kernels ---------------------------------------------
__global__ void k_zero_deg() {
    int i = blockIdx.x * blockDim.x + threadIdx.x;
    if (i < N_NODES) g_deg[i] = 0;
}

__global__ void k_count_deg(const int* __restrict__ col) {
    int e = blockIdx.x * blockDim.x + threadIdx.x;
    if (e < N_EDGES) atomicAdd(&g_deg[col[e]], 1);
}

// warp-shuffle based scan: 3 syncs per 1024-chunk
__global__ void k_scan_dis() {
    __shared__ int wsum[32];
    __shared__ int s_carry;
    int t = threadIdx.x, lane = t & 31, wd = t >> 5;
    if (t == 0) s_carry = 0;
    __syncthreads();
    for (int base = 0; base < N_NODES; base += 1024) {
        int idx = base + t;
        int v = (idx < N_NODES) ? g_deg[idx] : 0;
        int x = v;
#pragma unroll
        for (int off = 1; off < 32; off <<= 1) {
            int y = __shfl_up_sync(0xffffffffu, x, off);
            if (lane >= off) x += y;
        }
        if (lane == 31) wsum[wd] = x;
        __syncthreads();
        if (wd == 0) {
            int w = wsum[lane];
#pragma unroll
            for (int off = 1; off < 32; off <<= 1) {
                int y = __shfl_up_sync(0xffffffffu, w, off);
                if (lane >= off) w += y;
            }
            wsum[lane] = w;
        }
        __syncthreads();
        int warp_prefix = (wd == 0) ? 0 : wsum[wd - 1];
        int incl = warp_prefix + x;
        int carry = s_carry;
        if (idx < N_NODES) {
            int excl = carry + incl - v;
            g_indptr[idx] = excl;
            g_cursor[idx] = excl;
            g_dis[idx] = rsqrtf((float)(v + 1));
        }
        __syncthreads();
        if (t == 1023) s_carry = carry + incl;
        __syncthreads();
    }
    if (t == 0) g_indptr[N_NODES] = s_carry;
}

__global__ void k_fill_csr(const int* __restrict__ row, const int* __restrict__ col) {
    int e = blockIdx.x * blockDim.x + threadIdx.x;
    if (e < N_EDGES) {
        int r = row[e], c = col[e];
        float nrm = g_dis[r] * g_dis[c];
        int pos = atomicAdd(&g_cursor[c], 1);
        g_csr_src[pos] = r;
        g_csr_dst[pos] = c;
        g_csr_eid[pos] = e;
        g_csr_nrm[pos] = nrm;
    }
}

// ---------------- W transpose + bf16 hi/lo split (once) ---------------------
__global__ void k_split_w(const float* __restrict__ convs_W,
                          const float* __restrict__ fc0_W) {
    int idx = blockIdx.x * 256 + threadIdx.x;
    if (idx >= 10 * 16384) return;
    int l = idx >> 14;
    int kk = (idx >> 7) & 127;
    int n = idx & 127;
    float v = (l < 8) ? convs_W[idx] : fc0_W[idx - 8 * 16384];
    __nv_bfloat16 hi = __float2bfloat16(v);
    float lo = v - __bfloat162float(hi);
    int dst = (l << 14) + (n << 7) + kk;
    g_Wth[dst] = hi;
    g_Wtl[dst] = __float2bfloat16(lo);
}

// ---------------- persistent tensor-core node GEMM (bf16x2 3-pass) ----------
#define SGT_XH 0
#define SGT_XL 17408
#define SGT_WH 34816
#define SGT_WL 69632
#define SGT_BYTES 104448
#define GEMM_GRID 296
#define N_ROWTILES ((N_NODES + 63) / 64)

__device__ __forceinline__ void gemm_stage_X(char* smc, const float* __restrict__ Ain,
                                             int rowBase, int tid, int M) {
    const float4* A4 = (const float4*)Ain;
    uint32_t* Xh32 = (uint32_t*)(smc + SGT_XH);
    uint32_t* Xl32 = (uint32_t*)(smc + SGT_XL);
#pragma unroll
    for (int i = 0; i < 8; i++) {
        int idx = tid + i * 256;
        int rr = idx >> 5, c4 = idx & 31;
        float4 v = make_float4(0.f, 0.f, 0.f, 0.f);
        if (rowBase + rr < M) v = A4[(rowBase + rr) * 32 + c4];
        __nv_bfloat16 h0 = __float2bfloat16(v.x);
        __nv_bfloat16 h1 = __float2bfloat16(v.y);
        __nv_bfloat16 h2 = __float2bfloat16(v.z);
        __nv_bfloat16 h3 = __float2bfloat16(v.w);
        uint32_t hp0 = (uint32_t)__bfloat16_as_ushort(h0) |
                       ((uint32_t)__bfloat16_as_ushort(h1) << 16);
        uint32_t hp1 = (uint32_t)__bfloat16_as_ushort(h2) |
                       ((uint32_t)__bfloat16_as_ushort(h3) << 16);
        uint32_t lp0 = pack_bf16(v.x - __bfloat162float(h0), v.y - __bfloat162float(h1));
        uint32_t lp1 = pack_bf16(v.z - __bfloat162float(h2), v.w - __bfloat162float(h3));
        int o = rr * 68 + c4 * 2;
        *(uint2*)&Xh32[o] = make_uint2(hp0, hp1);
        *(uint2*)&Xl32[o] = make_uint2(lp0, lp1);
    }
}

__device__ __forceinline__ void gemm_stage_W(char* smc, int layer, int tid) {
    const uint4* Wh4 = (const uint4*)(g_Wth + layer * 16384);
    const uint4* Wl4 = (const uint4*)(g_Wtl + layer * 16384);
#pragma unroll
    for (int i = 0; i < 8; i++) {
        int idx = tid + i * 256;
        int rr = idx >> 4, c8 = idx & 15;
        *(uint4*)(smc + SGT_WH + rr * 272 + c8 * 16) = Wh4[rr * 16 + c8];
        *(uint4*)(smc + SGT_WL + rr * 272 + c8 * 16) = Wl4[rr * 16 + c8];
    }
}

__device__ __forceinline__ void gemm_tile_mma(char* smc, int lane, int wid,
                                              float acc[2][4][4]) {
#pragma unroll
    for (int mt = 0; mt < 2; mt++)
#pragma unroll
        for (int n = 0; n < 4; n++)
#pragma unroll
            for (int j = 0; j < 4; j++) acc[mt][n][j] = 0.f;

    int rblk = wid >> 2, cblk = wid & 3;
    uint32_t xh_sb = (uint32_t)__cvta_generic_to_shared(smc + SGT_XH);
    uint32_t xl_sb = (uint32_t)__cvta_generic_to_shared(smc + SGT_XL);
    uint32_t wh_sb = (uint32_t)__cvta_generic_to_shared(smc + SGT_WH);
    uint32_t wl_sb = (uint32_t)__cvta_generic_to_shared(smc + SGT_WL);

    int a_r = rblk * 32 + (lane & 7) + (lane & 8);
    int a_kel = (lane & 16) ? 8 : 0;
    uint32_t a_hi_base = xh_sb + (uint32_t)(a_r * 272 + a_kel * 2);
    uint32_t a_lo_base = xl_sb + (uint32_t)(a_r * 272 + a_kel * 2);
    int b_nloc = (lane & 7) + ((lane & 16) >> 1);
    int b_kel = (lane & 8);
    uint32_t b_rowoff = (uint32_t)((cblk * 32 + b_nloc) * 272 + b_kel * 2);

#pragma unroll
    for (int k = 0; k < 8; k++) {
        uint32_t ah[2][4], al[2][4];
        ldmx4(ah[0], a_hi_base + k * 32);
        ldmx4(ah[1], a_hi_base + 16 * 272 + k * 32);
        ldmx4(al[0], a_lo_base + k * 32);
        ldmx4(al[1], a_lo_base + 16 * 272 + k * 32);
        uint32_t bh[2][4], bl[2][4];
#pragma unroll
        for (int nb2 = 0; nb2 < 2; nb2++) {
            uint32_t off = b_rowoff + (uint32_t)(nb2 * 16 * 272) + k * 32;
            ldmx4(bh[nb2], wh_sb + off);
            ldmx4(bl[nb2], wl_sb + off);
        }
#pragma unroll
        for (int mt = 0; mt < 2; mt++)
#pragma unroll
            for (int nb = 0; nb < 4; nb++) {
                uint32_t b0h = bh[nb >> 1][(nb & 1) * 2], b1h = bh[nb >> 1][(nb & 1) * 2 + 1];
                uint32_t b0l = bl[nb >> 1][(nb & 1) * 2], b1l = bl[nb >> 1][(nb & 1) * 2 + 1];
                mma_bf16(acc[mt][nb], ah[mt], b0h, b1h);
                mma_bf16(acc[mt][nb], al[mt], b0h, b1h);
                mma_bf16(acc[mt][nb], ah[mt], b0l, b1l);
            }
    }
}

__device__ __forceinline__ void gemm_epi_fp32(float* __restrict__ out,
                                              const float* __restrict__ bias,
                                              int rowBase, int lane, int wid, int M,
                                              float acc[2][4][4]) {
    int g = lane >> 2, tg = lane & 3;
    int rblk = wid >> 2, cblk = wid & 3;
#pragma unroll
    for (int mt = 0; mt < 2; mt++) {
        int r0 = rowBase + rblk * 32 + mt * 16 + g;
#pragma unroll
        for (int nb = 0; nb < 4; nb++) {
            int c = cblk * 32 + nb * 8 + 2 * tg;
            float bv0 = 0.f, bv1 = 0.f;
            if (bias) { bv0 = bias[c]; bv1 = bias[c + 1]; }
            if (r0 < M)
                *(float2*)&out[r0 * 128 + c] = make_float2(acc[mt][nb][0] + bv0, acc[mt][nb][1] + bv1);
            if (r0 + 8 < M)
                *(float2*)&out[(r0 + 8) * 128 + c] = make_float2(acc[mt][nb][2] + bv0, acc[mt][nb][3] + bv1);
        }
    }
}

__device__ __forceinline__ void gemm_epi_fp16(int rowBase, int lane, int wid, int M,
                                              float acc[2][4][4]) {
    int g = lane >> 2, tg = lane & 3;
    int rblk = wid >> 2, cblk = wid & 3;
    __half2* oh = (__half2*)g_hwh;
#pragma unroll
    for (int mt = 0; mt < 2; mt++) {
        int r0 = rowBase + rblk * 32 + mt * 16 + g;
#pragma unroll
        for (int nb = 0; nb < 4; nb++) {
            int c = cblk * 32 + nb * 8 + 2 * tg;
            if (r0 < M)
                oh[(r0 * 128 + c) >> 1] = __floats2half2_rn(acc[mt][nb][0], acc[mt][nb][1]);
            if (r0 + 8 < M)
                oh[((r0 + 8) * 128 + c) >> 1] = __floats2half2_rn(acc[mt][nb][2], acc[mt][nb][3]);
        }
    }
}

// mode: 0 = conv layer (out g_hwh fp16), 3 = fc0 dual (g_A pass W8, g_B pass W9)
__global__ void __launch_bounds__(256, 2) k_sgemm_tc(
    const float* __restrict__ Aext, int a_sel, int mode, int layer,
    const float* __restrict__ bias, int M) {
    extern __shared__ char smc[];
    const float* Ain = a_sel ? g_h : Aext;
    int tid = threadIdx.x;
    int lane = tid & 31, wid = tid >> 5;

    if (mode != 3) gemm_stage_W(smc, layer, tid);

    float acc[2][4][4];
    for (int tile = blockIdx.x; tile < N_ROWTILES; tile += GEMM_GRID) {
        int rowBase = tile * 64;
        gemm_stage_X(smc, Ain, rowBase, tid, M);
        if (mode == 3) gemm_stage_W(smc, 8, tid);
        __syncthreads();

        gemm_tile_mma(smc, lane, wid, acc);
        if (mode == 3) {
            gemm_epi_fp32(g_A, bias, rowBase, lane, wid, M, acc);
            __syncthreads();
            gemm_stage_W(smc, 9, tid);
            __syncthreads();
            gemm_tile_mma(smc, lane, wid, acc);
            gemm_epi_fp32(g_B, nullptr, rowBase, lane, wid, M, acc);
        } else {
            gemm_epi_fp16(rowBase, lane, wid, M, acc);
        }
        __syncthreads();
    }
}

// ---------------- aggregation: h[n] = relu(self + sum + bias (+res)) --------
__global__ void k_agg(const float* __restrict__ bias, int residual) {
    int gw = (blockIdx.x * blockDim.x + threadIdx.x) >> 5;
    int lane = threadIdx.x & 31;
    int half = lane >> 4, hl = lane & 15;
    int n = gw * 2 + half;
    if (n >= N_NODES) return;

    const uint4* hw4 = (const uint4*)g_hwh;
    float d = g_dis[n];
    float ds = d * d;
    float4 acc0 = make_float4(0.f, 0.f, 0.f, 0.f);
    float4 acc1 = make_float4(0.f, 0.f, 0.f, 0.f);
    acc_h8(acc0, acc1, hw4[n * 16 + hl], ds);

    int e = g_indptr[n];
    int end = g_indptr[n + 1];
    for (; e + 8 <= end; e += 8) {
        int s[8]; float nr[8]; uint4 v[8];
#pragma unroll
        for (int j = 0; j < 8; j++) { s[j] = g_csr_src[e + j]; nr[j] = g_csr_nrm[e + j]; }
#pragma unroll
        for (int j = 0; j < 8; j++) v[j] = hw4[s[j] * 16 + hl];
#pragma unroll
        for (int j = 0; j < 8; j++) acc_h8(acc0, acc1, v[j], nr[j]);
    }
    if (e + 4 <= end) {
        int s[4]; float nr[4]; uint4 v[4];
#pragma unroll
        for (int j = 0; j < 4; j++) { s[j] = g_csr_src[e + j]; nr[j] = g_csr_nrm[e + j]; }
#pragma unroll
        for (int j = 0; j < 4; j++) v[j] = hw4[s[j] * 16 + hl];
#pragma unroll
        for (int j = 0; j < 4; j++) acc_h8(acc0, acc1, v[j], nr[j]);
        e += 4;
    }
    for (; e < end; e++)
        acc_h8(acc0, acc1, hw4[g_csr_src[e] * 16 + hl], g_csr_nrm[e]);

    float4 b0 = ((const float4*)bias)[hl * 2];
    float4 b1 = ((const float4*)bias)[hl * 2 + 1];
    acc0 = f4add(acc0, b0);
    acc1 = f4add(acc1, b1);
    if (residual) {
        acc0 = f4add(acc0, ((const float4*)g_h)[n * 32 + hl * 2]);
        acc1 = f4add(acc1, ((const float4*)g_h)[n * 32 + hl * 2 + 1]);
    }
    ((float4*)g_h)[n * 32 + hl * 2] = f4relu(acc0);
    ((float4*)g_h)[n * 32 + hl * 2 + 1] = f4relu(acc1);
}

// ---------------- persistent fused edge MLP (mma.sync fp16, k16) ------------
// One warp owns a 16-edge tile end-to-end (m16 x n128): private smem buf,
// __syncwarp only, no cross-warp combine. 16 independent pipelines/SM.
#define ESM_US 0                    // 8 warps x 16 x 272 B = 34816
#define ESM_WS 34816
#define ESM_B1 69632
#define ESM_W2 70144
#define ESM_BYTES 70656
#define N_TILES16 (N_EDGES / 16)
#define EDGE_GRID 296

__global__ void __launch_bounds__(256, 2) k_edge_mlp_fp16(
    const float* __restrict__ W1, const float* __restrict__ b1,
    const float* __restrict__ w2, const float* __restrict__ b2,
    float* __restrict__ out) {
    extern __shared__ char smc[];
    __half* Ws  = (__half*)(smc + ESM_WS);
    float* b1s  = (float*)(smc + ESM_B1);
    float* w2s  = (float*)(smc + ESM_W2);

    int tid = threadIdx.x;
    int lane = tid & 31, wid = tid >> 5;

    // --- stage W1^T (fp16), b1, w2 ONCE --------------------------------------
#pragma unroll 4
    for (int it = 0; it < 64; it++) {
        int i = it * 256 + tid;
        int kk = i >> 7, n = i & 127;
        Ws[n * 136 + kk] = __float2half_rn(W1[i]);
    }
    if (tid < 128) { b1s[tid] = b1[tid]; w2s[tid] = w2[tid]; }
    float b2v = b2[0];
    __syncthreads();

    int g = lane >> 2, tg = lane & 3;
    char* mybuf = smc + ESM_US + wid * (16 * 272);
    uint32_t us_sb = (uint32_t)__cvta_generic_to_shared(mybuf);
    uint32_t ws_sb = (uint32_t)__cvta_generic_to_shared(smc + ESM_WS);
    uint32_t a_base = us_sb +
        (uint32_t)(((lane & 7) + (lane & 8)) * 272 + ((lane & 16) ? 16 : 0));
    uint32_t b_base = ws_sb +
        (uint32_t)(((lane & 7) + ((lane & 16) >> 1)) * 272 + (lane & 8) * 2);

    const float4* A4 = (const float4*)g_A;
    const float4* B4 = (const float4*)g_B;

    for (int tile = blockIdx.x * 8 + wid; tile < N_TILES16; tile += EDGE_GRID * 8) {
        int p0 = tile * 16;

        // --- gather u = relu(A[src]+B[dst]) for 16 edges; 2 lanes/edge -------
        {
            int i = lane >> 1, h = lane & 1;
            int p = p0 + i;
            int r = g_csr_src[p] * 32, c = g_csr_dst[p] * 32;
            __half2* dst = (__half2*)(mybuf + i * 272 + h * 128);
#pragma unroll
            for (int q = 0; q < 16; q++) {
                float4 a = A4[r + h * 16 + q];
                float4 b = B4[c + h * 16 + q];
                dst[q * 2 + 0] = __floats2half2_rn(fmaxf(a.x + b.x, 0.f),
                                                   fmaxf(a.y + b.y, 0.f));
                dst[q * 2 + 1] = __floats2half2_rn(fmaxf(a.z + b.z, 0.f),
                                                   fmaxf(a.w + b.w, 0.f));
            }
        }
        __syncwarp();

        // --- fp16 mma: m16 (16 edges) x n128, warp-private -------------------
        float acc[16][4];
#pragma unroll
        for (int nb = 0; nb < 16; nb++)
#pragma unroll
            for (int j = 0; j < 4; j++) acc[nb][j] = 0.f;

#pragma unroll
        for (int k = 0; k < 8; k++) {
            uint32_t a[4];
            ldmx4(a, a_base + k * 32);
#pragma unroll
            for (int nb2 = 0; nb2 < 8; nb2++) {
                uint32_t bf[4];
                ldmx4(bf, b_base + (uint32_t)(nb2 * 16 * 272) + k * 32);
                mma_fp16(acc[nb2 * 2 + 0], a, bf[0], bf[1]);
                mma_fp16(acc[nb2 * 2 + 1], a, bf[2], bf[3]);
            }
        }

        // --- epilogue: relu(+b1).w2 dot, quad reduce, direct scatter ----------
        float p0v = 0.f, p1v = 0.f;
#pragma unroll
        for (int nb = 0; nb < 16; nb++) {
            int c0 = nb * 8 + 2 * tg;
            float wv0 = w2s[c0], wv1 = w2s[c0 + 1];
            float bb0 = b1s[c0], bb1 = b1s[c0 + 1];
            p0v += fmaxf(acc[nb][0] + bb0, 0.f) * wv0 + fmaxf(acc[nb][1] + bb1, 0.f) * wv1;
            p1v += fmaxf(acc[nb][2] + bb0, 0.f) * wv0 + fmaxf(acc[nb][3] + bb1, 0.f) * wv1;
        }
        p0v += __shfl_xor_sync(0xffffffffu, p0v, 1);
        p0v += __shfl_xor_sync(0xffffffffu, p0v, 2);
        p1v += __shfl_xor_sync(0xffffffffu, p1v, 1);
        p1v += __shfl_xor_sync(0xffffffffu, p1v, 2);
        if (tg == 0) {
            out[g_csr_eid[p0 + g]] = p0v + b2v;
            out[g_csr_eid[p0 + 8 + g]] = p1v + b2v;
        }
        __syncwarp();
    }
}

// ---------------- launch -----------------------------------------------------
extern "C" void kernel_launch(void* const* d_in, const int* in_sizes, int n_in,
                              void* d_out, int out_size) {
    const float* x       = (const float*)d_in[0];
    const int*   ei      = (const int*)d_in[1];
    const float* convs_W = (const float*)d_in[2];
    const float* convs_b = (const float*)d_in[3];
    const float* fc0_W   = (const float*)d_in[4];
    const float* fc0_b   = (const float*)d_in[5];
    const float* fc1_W   = (const float*)d_in[6];
    const float* fc1_b   = (const float*)d_in[7];
    const float* fc2_W   = (const float*)d_in[8];
    const float* fc2_b   = (const float*)d_in[9];
    float* out = (float*)d_out;

    const int* row = ei;
    const int* col = ei + N_EDGES;

    cudaFuncSetAttribute(k_sgemm_tc, cudaFuncAttributeMaxDynamicSharedMemorySize, SGT_BYTES);
    cudaFuncSetAttribute(k_edge_mlp_fp16, cudaFuncAttributeMaxDynamicSharedMemorySize, ESM_BYTES);

    const int GRID_AGG = (N_NODES * 16 + 255) / 256;

    // 1. setup (persistent sgemm L0 in the profiled 4th slot)
    k_split_w<<<(10 * 16384 + 255) / 256, 256>>>(convs_W, fc0_W);
    k_zero_deg<<<(N_NODES + 255) / 256, 256>>>();
    k_count_deg<<<(N_EDGES + 255) / 256, 256>>>(col);
    k_sgemm_tc<<<GEMM_GRID, 256, SGT_BYTES>>>(x, 0, 0, 0, nullptr, N_NODES);   // L0 GEMM
    k_scan_dis<<<1, 1024>>>();
    k_fill_csr<<<(N_EDGES + 255) / 256, 256>>>(row, col);
    k_agg<<<GRID_AGG, 256>>>(convs_b, 0);                                      // L0 agg

    // 2. GCN layers 1..7
    for (int l = 1; l < N_LAYERS; l++) {
        k_sgemm_tc<<<GEMM_GRID, 256, SGT_BYTES>>>(x, 1, 0, l, nullptr, N_NODES);
        k_agg<<<GRID_AGG, 256>>>(convs_b + l * CDIM, 1);
    }

    // 3. fused fc0 dual GEMM: g_A = h@W8 + b0, g_B = h@W9 (X staged once)
    k_sgemm_tc<<<GEMM_GRID, 256, SGT_BYTES>>>(nullptr, 1, 3, 8, fc0_b, N_NODES);

    // 4. persistent fused edge MLP, CSR order, warp-per-tile
    k_edge_mlp_fp16<<<EDGE_GRID, 256, ESM_BYTES>>>(fc1_W, fc1_b, fc2_W, fc2_b, out);
}